// round 4
// baseline (speedup 1.0000x reference)
#include <cuda_runtime.h>

#define NB 8
#define NA 120000
#define NM 64
#define TPB 256
#define APT 4                       // anchors per thread
#define SPAN (APT * TPB)            // anchors per block
#define GRIDX ((NA + SPAN - 1) / SPAN)
#define TOTAL_BLOCKS (GRIDX * NB)

__device__ float    g_cls[NB];
__device__ float    g_reg[NB];
__device__ int      g_pos[NB];
__device__ unsigned g_ctr;   // zero-init at module load; reset by last block each launch

__global__ __launch_bounds__(TPB, 5) void rn_loss_kernel(
    const float* __restrict__ gt,     // (B, M, 5): cx, cy, w, h, label
    const float* __restrict__ pcls,   // (B, A, 1)
    const float* __restrict__ preg,   // (B, A, 4)
    const float* __restrict__ anc,    // (1, A, 4): x1, y1, x2, y2
    float* __restrict__ out)          // (2,)
{
    __shared__ float4 s_corn[NM];   // gt corners x1,y1,x2,y2
    __shared__ float  s_area[NM];   // gt area (corner-derived, matches ref rounding)
    __shared__ float4 s_raw[NM];    // gt cx,cy,w,h (for regression targets)
    __shared__ float  s_c[TPB / 32], s_r[TPB / 32];
    __shared__ int    s_n[TPB / 32];

    const int img = blockIdx.y;
    const int tid = threadIdx.x;

    float mylab = -1.0f;
    if (tid < NM) {
        const float* g = gt + ((long)img * NM + tid) * 5;
        float cx = g[0], cy = g[1], w = g[2], h = g[3];
        mylab = g[4];
        float x1 = cx - 0.5f * w, y1 = cy - 0.5f * h;
        float x2 = cx + 0.5f * w, y2 = cy + 0.5f * h;
        s_corn[tid] = make_float4(x1, y1, x2, y2);
        s_area[tid] = (x2 - x1) * (y2 - y1);
        s_raw[tid]  = make_float4(cx, cy, w, h);
    }
    // valid labels form a prefix (index < ngt) by construction; this also barriers
    const int ngt = __syncthreads_count(tid < NM && mylab != -1.0f);

    const int abase = blockIdx.x * SPAN + tid;

    float4 A4[APT];
    float  Ca[APT];
    float  Ib[APT], Sb[APT];
    int    mb[APT];

    #pragma unroll
    for (int j = 0; j < APT; ++j) {
        int a = abase + j * TPB;
        if (a >= NA) a = 0;           // safe address; contribution gated later
        A4[j] = __ldg((const float4*)anc + a);
        Ca[j] = (A4[j].z - A4[j].x) * (A4[j].w - A4[j].y);
        Ib[j] = 0.f; Sb[j] = 1.f; mb[j] = 0;
    }

    // single running-best chain per anchor; cross-mult compare, div-free.
    // iou_m = I/(S - I) monotone in I/S  =>  I*Sb > Ib*S picks larger iou.
    // init (0,1): first I>0 wins, matching the strict-> running max from m=0.
    #pragma unroll 2
    for (int m = 0; m < ngt; ++m) {
        const float4 gq = s_corn[m];
        const float  ar = s_area[m];
        #pragma unroll
        for (int j = 0; j < APT; ++j) {
            float w = fminf(A4[j].z, gq.z) - fmaxf(A4[j].x, gq.x);
            float h = fminf(A4[j].w, gq.w) - fmaxf(A4[j].y, gq.y);
            // one-clamp: w<=0 -> I=0 ; w>0,h<0 -> I<0 (can never win);
            // any winner has I>0 => equals the reference's clamped product.
            float I = fmaxf(w, 0.f) * h;
            float S = Ca[j] + ar;
            bool  c = I * Sb[j] > Ib[j] * S;
            Ib[j] = c ? I : Ib[j];
            Sb[j] = c ? S : Sb[j];
            mb[j] = c ? m : mb[j];
        }
    }

    float cterm = 0.f, rterm = 0.f;
    int   npos  = 0;

    #pragma unroll
    for (int j = 0; j < APT; ++j) {
        const int a = abase + j * TPB;
        if (a >= NA) continue;
        // iou_max >= 0.5 <=> 3*Ib >= Sb ;  iou_max < 0.4 <=> 7*Ib < 2*Sb
        const bool pos = (3.0f * Ib[j] >= Sb[j]);
        const bool neg = (7.0f * Ib[j] < 2.0f * Sb[j]);
        const float p = __ldg(pcls + (long)img * NA + a);

        if (pos) {
            npos += 1;
            // C == 1 and every valid label is in [0,1) => always class 0:
            // the one-hot target is 1.0 for the single class.
            float qq = 1.0f - p;
            cterm += 0.25f * qq * qq * (-logf(p));

            const float aw  = A4[j].z - A4[j].x;
            const float ah  = A4[j].w - A4[j].y;
            const float acx = A4[j].x + 0.5f * aw;
            const float acy = A4[j].y + 0.5f * ah;
            const float4 gr = s_raw[mb[j]];
            const float gw = fmaxf(gr.z, 1.0f);
            const float gh = fmaxf(gr.w, 1.0f);
            const float t0 = ((gr.x - acx) / aw) / 0.1f;
            const float t1 = ((gr.y - acy) / ah) / 0.1f;
            const float t2 = logf(gw / aw) / 0.2f;
            const float t3 = logf(gh / ah) / 0.2f;

            const float4 rg = __ldg((const float4*)preg + (long)img * NA + a);
            const float d0 = fabsf(t0 - rg.x);
            const float d1 = fabsf(t1 - rg.y);
            const float d2 = fabsf(t2 - rg.z);
            const float d3 = fabsf(t3 - rg.w);
            const float TH = (float)(1.0 / 9.0);
            const float CC = (float)(0.5 / 9.0);
            rterm += (d0 <= TH) ? 4.5f * d0 * d0 : d0 - CC;
            rterm += (d1 <= TH) ? 4.5f * d1 * d1 : d1 - CC;
            rterm += (d2 <= TH) ? 4.5f * d2 * d2 : d2 - CC;
            rterm += (d3 <= TH) ? 4.5f * d3 * d3 : d3 - CC;
        } else if (neg) {
            cterm += 0.75f * p * p * (-logf(1.0f - p));
        }
        // 0.4 <= iou < 0.5: ignore
    }

    // warp reduction
    const unsigned mask = 0xFFFFFFFFu;
    #pragma unroll
    for (int off = 16; off; off >>= 1) {
        cterm += __shfl_down_sync(mask, cterm, off);
        rterm += __shfl_down_sync(mask, rterm, off);
        npos  += __shfl_down_sync(mask, npos, off);
    }
    const int wid = tid >> 5, lid = tid & 31;
    if (lid == 0) { s_c[wid] = cterm; s_r[wid] = rterm; s_n[wid] = npos; }
    __syncthreads();

    if (tid == 0) {
        float c = 0.f, r = 0.f; int n = 0;
        #pragma unroll
        for (int i = 0; i < TPB / 32; ++i) { c += s_c[i]; r += s_r[i]; n += s_n[i]; }
        atomicAdd(&g_cls[img], c);
        atomicAdd(&g_reg[img], r);
        atomicAdd(&g_pos[img], n);

        __threadfence();
        unsigned v = atomicAdd(&g_ctr, 1u);
        if (v == (unsigned)(TOTAL_BLOCKS - 1)) {
            // last block: all other blocks' accumulations are visible
            float cs = 0.f, rs = 0.f;
            #pragma unroll
            for (int i = 0; i < NB; ++i) {
                float cv = atomicAdd(&g_cls[i], 0.f);   // atomic read (fresh)
                float rv = atomicAdd(&g_reg[i], 0.f);
                int   nv = atomicAdd(&g_pos[i], 0);
                float np = (float)nv;
                cs += cv / fmaxf(np, 1.0f);
                rs += (nv > 0) ? (rv / fmaxf(np * 4.0f, 1.0f)) : 0.0f;
            }
            out[0] = cs / (float)NB;
            out[1] = rs / (float)NB;
            // reset state for the next graph replay
            #pragma unroll
            for (int i = 0; i < NB; ++i) { g_cls[i] = 0.f; g_reg[i] = 0.f; g_pos[i] = 0; }
            g_ctr = 0u;
        }
    }
}

extern "C" void kernel_launch(void* const* d_in, const int* in_sizes, int n_in,
                              void* d_out, int out_size) {
    const float* gt = (const float*)d_in[0];   // y_true_tmp (8,64,5)
    const float* pc = (const float*)d_in[1];   // y_classifs (8,120000,1)
    const float* pr = (const float*)d_in[2];   // y_regressions (8,120000,4)
    const float* an = (const float*)d_in[3];   // anchors (1,120000,4)

    dim3 grid(GRIDX, NB);
    rn_loss_kernel<<<grid, TPB>>>(gt, pc, pr, an, (float*)d_out);
}

// round 5
// speedup vs baseline: 1.1020x; 1.1020x over previous
#include <cuda_runtime.h>

#define NB 8
#define NA 120000
#define NM 64
#define TPB 128
#define APT 2                       // anchors per thread
#define SPAN (APT * TPB)            // anchors per block = 256
#define GRIDX ((NA + SPAN - 1) / SPAN)
#define TOTAL_BLOCKS (GRIDX * NB)

__device__ float    g_cls[NB];
__device__ float    g_reg[NB];
__device__ int      g_pos[NB];
__device__ unsigned g_ctr;   // zero-init at module load; reset by last block each launch

__global__ __launch_bounds__(TPB, 12) void rn_loss_kernel(
    const float* __restrict__ gt,     // (B, M, 5): cx, cy, w, h, label
    const float* __restrict__ pcls,   // (B, A, 1)
    const float* __restrict__ preg,   // (B, A, 4)
    const float* __restrict__ anc,    // (1, A, 4): x1, y1, x2, y2
    float* __restrict__ out)          // (2,)
{
    __shared__ float4 s_corn[NM];   // gt corners x1,y1,x2,y2
    __shared__ float  s_area[NM];   // gt area (corner-derived, matches ref rounding)
    __shared__ float4 s_raw[NM];    // gt cx,cy,w,h (for regression targets)
    __shared__ float  s_c[TPB / 32], s_r[TPB / 32];
    __shared__ int    s_n[TPB / 32];

    const int img = blockIdx.y;
    const int tid = threadIdx.x;

    float mylab = -1.0f;
    if (tid < NM) {
        const float* g = gt + (img * NM + tid) * 5;
        float cx = g[0], cy = g[1], w = g[2], h = g[3];
        mylab = g[4];
        float x1 = cx - 0.5f * w, y1 = cy - 0.5f * h;
        float x2 = cx + 0.5f * w, y2 = cy + 0.5f * h;
        s_corn[tid] = make_float4(x1, y1, x2, y2);
        s_area[tid] = (x2 - x1) * (y2 - y1);
        s_raw[tid]  = make_float4(cx, cy, w, h);
    }
    // valid labels form a prefix (index < ngt) by construction; this also barriers
    const int ngt = __syncthreads_count(tid < NM && mylab != -1.0f);

    const int abase = blockIdx.x * SPAN + tid;
    const int ibase = img * NA;          // 32-bit: 8*120000 < 2^31

    float4 A4[APT];
    float  Ca[APT];
    float  Ib[APT], Sb[APT];
    int    mb[APT];

    #pragma unroll
    for (int j = 0; j < APT; ++j) {
        int a = abase + j * TPB;
        if (a >= NA) a = 0;           // safe address; contribution gated later
        A4[j] = __ldg((const float4*)anc + a);
        Ca[j] = (A4[j].z - A4[j].x) * (A4[j].w - A4[j].y);
        Ib[j] = 0.f; Sb[j] = 1.f; mb[j] = 0;
    }

    // single running-best chain per anchor; cross-mult compare, div-free.
    // iou_m = I/(S - I) monotone in I/S  =>  I*Sb > Ib*S picks larger iou.
    // init (0,1): first I>0 wins, matching the strict-> running max from m=0.
    #pragma unroll 4
    for (int m = 0; m < ngt; ++m) {
        const float4 gq = s_corn[m];
        const float  ar = s_area[m];
        #pragma unroll
        for (int j = 0; j < APT; ++j) {
            float w = fminf(A4[j].z, gq.z) - fmaxf(A4[j].x, gq.x);
            float h = fminf(A4[j].w, gq.w) - fmaxf(A4[j].y, gq.y);
            // one-clamp: w<=0 -> I=0 ; w>0,h<0 -> I<0 (can never win);
            // any winner has I>0 => equals the reference's clamped product.
            float I = fmaxf(w, 0.f) * h;
            float S = Ca[j] + ar;
            bool  c = I * Sb[j] > Ib[j] * S;
            Ib[j] = c ? I : Ib[j];
            Sb[j] = c ? S : Sb[j];
            mb[j] = c ? m : mb[j];
        }
    }

    float cterm = 0.f, rterm = 0.f;
    int   npos  = 0;

    #pragma unroll
    for (int j = 0; j < APT; ++j) {
        const int a = abase + j * TPB;
        if (a >= NA) continue;
        // iou_max >= 0.5 <=> 3*Ib >= Sb ;  iou_max < 0.4 <=> 7*Ib < 2*Sb
        const bool pos = (3.0f * Ib[j] >= Sb[j]);
        const bool neg = (7.0f * Ib[j] < 2.0f * Sb[j]);
        const float p = __ldg(pcls + ibase + a);

        if (pos) {
            npos += 1;
            // C == 1 and every valid label is in [0,1) => always class 0:
            // the one-hot target is 1.0 for the single class.
            float qq = 1.0f - p;
            cterm += 0.25f * qq * qq * (-logf(p));

            const float aw  = A4[j].z - A4[j].x;
            const float ah  = A4[j].w - A4[j].y;
            const float acx = A4[j].x + 0.5f * aw;
            const float acy = A4[j].y + 0.5f * ah;
            const float4 gr = s_raw[mb[j]];
            const float gw = fmaxf(gr.z, 1.0f);
            const float gh = fmaxf(gr.w, 1.0f);
            const float t0 = ((gr.x - acx) / aw) / 0.1f;
            const float t1 = ((gr.y - acy) / ah) / 0.1f;
            const float t2 = logf(gw / aw) / 0.2f;
            const float t3 = logf(gh / ah) / 0.2f;

            const float4 rg = __ldg((const float4*)preg + ibase + a);
            const float d0 = fabsf(t0 - rg.x);
            const float d1 = fabsf(t1 - rg.y);
            const float d2 = fabsf(t2 - rg.z);
            const float d3 = fabsf(t3 - rg.w);
            const float TH = (float)(1.0 / 9.0);
            const float CC = (float)(0.5 / 9.0);
            rterm += (d0 <= TH) ? 4.5f * d0 * d0 : d0 - CC;
            rterm += (d1 <= TH) ? 4.5f * d1 * d1 : d1 - CC;
            rterm += (d2 <= TH) ? 4.5f * d2 * d2 : d2 - CC;
            rterm += (d3 <= TH) ? 4.5f * d3 * d3 : d3 - CC;
        } else if (neg) {
            cterm += 0.75f * p * p * (-logf(1.0f - p));
        }
        // 0.4 <= iou < 0.5: ignore
    }

    // warp reduction
    const unsigned mask = 0xFFFFFFFFu;
    #pragma unroll
    for (int off = 16; off; off >>= 1) {
        cterm += __shfl_down_sync(mask, cterm, off);
        rterm += __shfl_down_sync(mask, rterm, off);
        npos  += __shfl_down_sync(mask, npos, off);
    }
    const int wid = tid >> 5, lid = tid & 31;
    if (lid == 0) { s_c[wid] = cterm; s_r[wid] = rterm; s_n[wid] = npos; }
    __syncthreads();

    if (tid == 0) {
        float c = 0.f, r = 0.f; int n = 0;
        #pragma unroll
        for (int i = 0; i < TPB / 32; ++i) { c += s_c[i]; r += s_r[i]; n += s_n[i]; }
        atomicAdd(&g_cls[img], c);
        atomicAdd(&g_reg[img], r);
        atomicAdd(&g_pos[img], n);

        __threadfence();
        unsigned v = atomicAdd(&g_ctr, 1u);
        if (v == (unsigned)(TOTAL_BLOCKS - 1)) {
            // last block: all other blocks' accumulations are visible
            float cs = 0.f, rs = 0.f;
            #pragma unroll
            for (int i = 0; i < NB; ++i) {
                float cv = atomicAdd(&g_cls[i], 0.f);   // atomic read (fresh)
                float rv = atomicAdd(&g_reg[i], 0.f);
                int   nv = atomicAdd(&g_pos[i], 0);
                float np = (float)nv;
                cs += cv / fmaxf(np, 1.0f);
                rs += (nv > 0) ? (rv / fmaxf(np * 4.0f, 1.0f)) : 0.0f;
            }
            out[0] = cs / (float)NB;
            out[1] = rs / (float)NB;
            // reset state for the next graph replay
            #pragma unroll
            for (int i = 0; i < NB; ++i) { g_cls[i] = 0.f; g_reg[i] = 0.f; g_pos[i] = 0; }
            g_ctr = 0u;
        }
    }
}

extern "C" void kernel_launch(void* const* d_in, const int* in_sizes, int n_in,
                              void* d_out, int out_size) {
    const float* gt = (const float*)d_in[0];   // y_true_tmp (8,64,5)
    const float* pc = (const float*)d_in[1];   // y_classifs (8,120000,1)
    const float* pr = (const float*)d_in[2];   // y_regressions (8,120000,4)
    const float* an = (const float*)d_in[3];   // anchors (1,120000,4)

    dim3 grid(GRIDX, NB);
    rn_loss_kernel<<<grid, TPB>>>(gt, pc, pr, an, (float*)d_out);
}

// round 6
// speedup vs baseline: 1.1636x; 1.0559x over previous
#include <cuda_runtime.h>

#define NB 8
#define NA 120000
#define NM 64
#define TPB 128
#define APT 2                       // anchors per thread
#define SPAN (APT * TPB)            // anchors per block = 256
#define GRIDX ((NA + SPAN - 1) / SPAN)
#define TOTAL_BLOCKS (GRIDX * NB)

__device__ float    g_cls[NB];
__device__ float    g_reg[NB];
__device__ int      g_pos[NB];
__device__ unsigned g_ctr;   // zero-init at module load; reset by last block each launch

__global__ __launch_bounds__(TPB, 12) void rn_loss_kernel(
    const float* __restrict__ gt,     // (B, M, 5): cx, cy, w, h, label
    const float* __restrict__ pcls,   // (B, A, 1)
    const float* __restrict__ preg,   // (B, A, 4)
    const float* __restrict__ anc,    // (1, A, 4): x1, y1, x2, y2
    float* __restrict__ out)          // (2,)
{
    __shared__ float4 s_corn[NM];   // gt corners x1,y1,x2,y2
    __shared__ float  s_area[NM];   // gt area (corner-derived, matches ref rounding)
    __shared__ float4 s_raw[NM];    // gt cx,cy,w,h (for regression targets)
    __shared__ float  s_c[TPB / 32], s_r[TPB / 32];
    __shared__ int    s_n[TPB / 32];

    const int img = blockIdx.y;
    const int tid = threadIdx.x;

    float mylab = -1.0f;
    if (tid < NM) {
        const float* g = gt + (img * NM + tid) * 5;
        float cx = g[0], cy = g[1], w = g[2], h = g[3];
        mylab = g[4];
        float x1 = cx - 0.5f * w, y1 = cy - 0.5f * h;
        float x2 = cx + 0.5f * w, y2 = cy + 0.5f * h;
        s_corn[tid] = make_float4(x1, y1, x2, y2);
        s_area[tid] = (x2 - x1) * (y2 - y1);
        s_raw[tid]  = make_float4(cx, cy, w, h);
    }
    // valid labels form a prefix (index < ngt) by construction; this also barriers
    const int ngt = __syncthreads_count(tid < NM && mylab != -1.0f);

    const int abase = blockIdx.x * SPAN + tid;
    const int ibase = img * NA;          // 32-bit: 8*120000 < 2^31

    float4 A4[APT];
    float  Ca[APT];
    float  Ib[APT], Sb[APT];
    int    mb[APT];

    #pragma unroll
    for (int j = 0; j < APT; ++j) {
        int a = abase + j * TPB;
        if (a >= NA) a = 0;           // safe address; contribution gated later
        A4[j] = __ldg((const float4*)anc + a);
        Ca[j] = (A4[j].z - A4[j].x) * (A4[j].w - A4[j].y);
        Ib[j] = 0.f; Sb[j] = 1.f; mb[j] = 0;
    }

    // single running-best chain per anchor; cross-mult compare, div-free.
    // iou_m = I/(S - I) monotone in I/S  =>  I*Sb > Ib*S picks larger iou.
    // init (0,1): first I>0 wins, matching the strict-> running max from m=0.
    #pragma unroll 4
    for (int m = 0; m < ngt; ++m) {
        const float4 gq = s_corn[m];
        const float  ar = s_area[m];
        #pragma unroll
        for (int j = 0; j < APT; ++j) {
            float w = fminf(A4[j].z, gq.z) - fmaxf(A4[j].x, gq.x);
            float h = fminf(A4[j].w, gq.w) - fmaxf(A4[j].y, gq.y);
            // one-clamp: w<=0 -> I=0 ; w>0,h<0 -> I<0 (can never win);
            // any winner has I>0 => equals the reference's clamped product.
            float I = fmaxf(w, 0.f) * h;
            float S = Ca[j] + ar;
            bool  c = I * Sb[j] > Ib[j] * S;
            Ib[j] = c ? I : Ib[j];
            Sb[j] = c ? S : Sb[j];
            mb[j] = c ? m : mb[j];
        }
    }

    float cterm = 0.f, rterm = 0.f;
    int   npos  = 0;

    #pragma unroll
    for (int j = 0; j < APT; ++j) {
        const int a = abase + j * TPB;
        if (a >= NA) continue;
        // iou_max >= 0.5 <=> 3*Ib >= Sb ;  iou_max < 0.4 <=> 7*Ib < 2*Sb
        const bool pos = (3.0f * Ib[j] >= Sb[j]);
        const bool neg = (7.0f * Ib[j] < 2.0f * Sb[j]);
        const float p = __ldg(pcls + ibase + a);

        if (pos) {
            npos += 1;
            // C == 1 and every valid label is in [0,1) => always class 0:
            // the one-hot target is 1.0 for the single class.
            float qq = 1.0f - p;
            cterm += 0.25f * qq * qq * (-__logf(p));

            const float aw  = A4[j].z - A4[j].x;
            const float ah  = A4[j].w - A4[j].y;
            const float acx = A4[j].x + 0.5f * aw;
            const float acy = A4[j].y + 0.5f * ah;
            const float4 gr = s_raw[mb[j]];
            const float gw = fmaxf(gr.z, 1.0f);
            const float gh = fmaxf(gr.w, 1.0f);
            const float t0 = ((gr.x - acx) / aw) / 0.1f;
            const float t1 = ((gr.y - acy) / ah) / 0.1f;
            const float t2 = logf(gw / aw) / 0.2f;   // rare path: keep precise
            const float t3 = logf(gh / ah) / 0.2f;

            const float4 rg = __ldg((const float4*)preg + ibase + a);
            const float d0 = fabsf(t0 - rg.x);
            const float d1 = fabsf(t1 - rg.y);
            const float d2 = fabsf(t2 - rg.z);
            const float d3 = fabsf(t3 - rg.w);
            const float TH = (float)(1.0 / 9.0);
            const float CC = (float)(0.5 / 9.0);
            rterm += (d0 <= TH) ? 4.5f * d0 * d0 : d0 - CC;
            rterm += (d1 <= TH) ? 4.5f * d1 * d1 : d1 - CC;
            rterm += (d2 <= TH) ? 4.5f * d2 * d2 : d2 - CC;
            rterm += (d3 <= TH) ? 4.5f * d3 * d3 : d3 - CC;
        } else if (neg) {
            // hot path (~95% of anchors): fast log (MUFU.LG2)
            cterm += 0.75f * p * p * (-__logf(1.0f - p));
        }
        // 0.4 <= iou < 0.5: ignore
    }

    // warp reduction
    const unsigned mask = 0xFFFFFFFFu;
    #pragma unroll
    for (int off = 16; off; off >>= 1) {
        cterm += __shfl_down_sync(mask, cterm, off);
        rterm += __shfl_down_sync(mask, rterm, off);
        npos  += __shfl_down_sync(mask, npos, off);
    }
    const int wid = tid >> 5, lid = tid & 31;
    if (lid == 0) { s_c[wid] = cterm; s_r[wid] = rterm; s_n[wid] = npos; }
    __syncthreads();

    if (tid == 0) {
        float c = 0.f, r = 0.f; int n = 0;
        #pragma unroll
        for (int i = 0; i < TPB / 32; ++i) { c += s_c[i]; r += s_r[i]; n += s_n[i]; }
        atomicAdd(&g_cls[img], c);
        atomicAdd(&g_reg[img], r);
        atomicAdd(&g_pos[img], n);

        __threadfence();
        unsigned v = atomicAdd(&g_ctr, 1u);
        if (v == (unsigned)(TOTAL_BLOCKS - 1)) {
            // last block: all other blocks' accumulations are visible
            float cs = 0.f, rs = 0.f;
            #pragma unroll
            for (int i = 0; i < NB; ++i) {
                float cv = atomicAdd(&g_cls[i], 0.f);   // atomic read (fresh)
                float rv = atomicAdd(&g_reg[i], 0.f);
                int   nv = atomicAdd(&g_pos[i], 0);
                float np = (float)nv;
                cs += cv / fmaxf(np, 1.0f);
                rs += (nv > 0) ? (rv / fmaxf(np * 4.0f, 1.0f)) : 0.0f;
            }
            out[0] = cs / (float)NB;
            out[1] = rs / (float)NB;
            // reset state for the next graph replay
            #pragma unroll
            for (int i = 0; i < NB; ++i) { g_cls[i] = 0.f; g_reg[i] = 0.f; g_pos[i] = 0; }
            g_ctr = 0u;
        }
    }
}

extern "C" void kernel_launch(void* const* d_in, const int* in_sizes, int n_in,
                              void* d_out, int out_size) {
    const float* gt = (const float*)d_in[0];   // y_true_tmp (8,64,5)
    const float* pc = (const float*)d_in[1];   // y_classifs (8,120000,1)
    const float* pr = (const float*)d_in[2];   // y_regressions (8,120000,4)
    const float* an = (const float*)d_in[3];   // anchors (1,120000,4)

    dim3 grid(GRIDX, NB);
    rn_loss_kernel<<<grid, TPB>>>(gt, pc, pr, an, (float*)d_out);
}